// round 7
// baseline (speedup 1.0000x reference)
#include <cuda_runtime.h>

// Cox partial-likelihood loss, n = 8192, single fused kernel.
// loss = -mean_i[ (theta_i - log(sum_{j: t_j>=t_i} exp(theta_j) + eps)) * e_i ]
//
// One launch. Grid = (jchunks=32, itiles=4) = 128 blocks of 256 threads.
// Block (jc, it):
//   1. stages (t_j, exp(risk_j)) for its 256-j chunk into smem (exp inline)
//   2. accumulates predicated sums for its 2048 i's (IPT=8 register blocking)
//   3. writes per-(i, jc) partials to __device__ scratch
//   4. threadfence + int atomicAdd counter; the LAST block per i-tile reduces
//      the 32 partials per i in fixed order, applies log/event mask, does a
//      fixed-order block reduction; the last finalizer sums the 4 tile sums
//      in fixed order, writes -sum/n, and resets counters for graph replay.
//
// All floating-point summation is fixed-order -> deterministic output.
// Integer atomics only sequence the phases. No device allocations.

#define N_MAX    8192
#define BLOCK    256
#define IPT      8
#define JCH      256
#define JCHUNKS_MAX 32
#define ITILES_MAX  8
#define EPS_F    1e-8f

__device__ float g_part[JCHUNKS_MAX * N_MAX];   // [jc][i]
__device__ float g_tsum[ITILES_MAX];            // per-i-tile sums
__device__ int   g_done_it[ITILES_MAX];         // zero-init at module load
__device__ int   g_done_final;                  // zero-init at module load

__global__ __launch_bounds__(BLOCK) void cox_fused_kernel(
    const float* __restrict__ risk,
    const float* __restrict__ t,
    const float* __restrict__ e,
    float* __restrict__ out,
    int n, int jchunks, int itiles)
{
    __shared__ float2 te[JCH];
    __shared__ float  red[BLOCK];
    __shared__ int    flag;

    const int jc  = blockIdx.x;
    const int it  = blockIdx.y;
    const int tid = threadIdx.x;

    // ---- stage j-chunk: (t_j, exp(theta_j)) interleaved for 1-LDS broadcast
    const int j0 = jc * JCH;
    te[tid] = make_float2(t[j0 + tid], expf(risk[j0 + tid]));
    __syncthreads();

    // ---- pair phase: 2048 i's per block, 8 per thread
    const int ibase = it * (BLOCK * IPT);

    float ti[IPT];
    float s[IPT];
#pragma unroll
    for (int k = 0; k < IPT; k++) {
        ti[k] = t[ibase + k * BLOCK + tid];   // coalesced
        s[k]  = 0.0f;
    }

#pragma unroll 4
    for (int j = 0; j < JCH; j++) {
        const float2 p = te[j];               // single LDS.64 broadcast
#pragma unroll
        for (int k = 0; k < IPT; k++) {
            if (p.x >= ti[k]) s[k] += p.y;    // FSETP + @P FADD
        }
    }

#pragma unroll
    for (int k = 0; k < IPT; k++) {
        g_part[jc * n + ibase + k * BLOCK + tid] = s[k];
    }

    // ---- make partials visible, elect last block of this i-tile
    __threadfence();
    __syncthreads();
    if (tid == 0) {
        int v = atomicAdd(&g_done_it[it], 1);
        flag = (v == jchunks - 1);
    }
    __syncthreads();
    if (!flag) return;

    // ---- finalize this i-tile (only the last (jc, it) block gets here)
    __threadfence();   // acquire: partials from all jc blocks now visible

    float acc = 0.0f;
#pragma unroll
    for (int k = 0; k < IPT; k++) {
        const int i = ibase + k * BLOCK + tid;
        float S = 0.0f;
        for (int c = 0; c < jchunks; c++) {        // fixed order
            S += __ldcg(&g_part[c * n + i]);       // L2 read (cross-SM data)
        }
        acc += (risk[i] - logf(S + EPS_F)) * e[i]; // fixed order
    }

    // fixed-order block reduction of 256 values
    red[tid] = acc;
    __syncthreads();
#pragma unroll
    for (int off = BLOCK / 2; off >= 64; off >>= 1) {
        if (tid < off) red[tid] += red[tid + off];
        __syncthreads();
    }
    if (tid < 32) {
        float v = red[tid] + red[tid + 32];
#pragma unroll
        for (int off = 16; off > 0; off >>= 1)
            v += __shfl_down_sync(0xffffffffu, v, off);
        if (tid == 0) {
            g_tsum[it] = v;
            __threadfence();
            int v2 = atomicAdd(&g_done_final, 1);
            flag = (v2 == itiles - 1);
        }
    }
    __syncthreads();
    if (!flag) return;

    // ---- very last block: final fixed-order sum, output, counter reset
    if (tid == 0) {
        __threadfence();
        float total = 0.0f;
        for (int k = 0; k < itiles; k++)           // fixed order
            total += __ldcg(&g_tsum[k]);
        out[0] = -total / (float)n;

        // reset counters so the next graph replay starts clean
        g_done_final = 0;
        for (int k = 0; k < itiles; k++) g_done_it[k] = 0;
        __threadfence();
    }
}

// ---------------------------------------------------------------- launch
extern "C" void kernel_launch(void* const* d_in, const int* in_sizes, int n_in,
                              void* d_out, int out_size) {
    const float* risk = (const float*)d_in[0];
    const float* t    = (const float*)d_in[1];
    const float* e    = (const float*)d_in[2];
    float* out = (float*)d_out;

    const int n = in_sizes[0];               // 8192
    const int jchunks = n / JCH;             // 32
    const int itiles  = n / (BLOCK * IPT);   // 4

    cox_fused_kernel<<<dim3(jchunks, itiles), BLOCK>>>(
        risk, t, e, out, n, jchunks, itiles);
}

// round 8
// speedup vs baseline: 1.4250x; 1.4250x over previous
#include <cuda_runtime.h>

// Cox partial-likelihood loss, n = 8192, single fused kernel.
// loss = -mean_i[ (theta_i - log(sum_{j: t_j>=t_i} exp(theta_j) + eps)) * e_i ]
//
// Grid = (jchunks=32, itiles=4) = 128 blocks (1 per SM, balanced) of 512
// threads (16 warps -> 4 warps/SMSP for latency hiding).
//
// Pair inner loop uses FSET (mask-as-data, 1.0f/0.0f) + FFMA: 2 fixed-lat-4
// instructions per pair, no pred-as-guard 13-cycle dependency.
//
// Decoupled finalize: last block per i-tile (int-atomic election) reduces the
// 32 per-chunk partials per i in FIXED order (deterministic fp), applies
// log/event mask, block-reduces; the very last finalizer sums 4 tile sums in
// fixed order, writes -sum/n, resets counters for graph replay.

#define N_MAX    8192
#define BLOCK    512
#define IPT      4          // i's per thread  (i-tile = 2048)
#define JCH      256        // j's per chunk
#define JCHUNKS_MAX 32
#define ITILES_MAX  8
#define EPS_F    1e-8f

__device__ float g_part[JCHUNKS_MAX * N_MAX];   // [jc][i]
__device__ float g_tsum[ITILES_MAX];
__device__ int   g_done_it[ITILES_MAX];         // zero-init
__device__ int   g_done_final;                  // zero-init

__global__ __launch_bounds__(BLOCK) void cox_fused_kernel(
    const float* __restrict__ risk,
    const float* __restrict__ t,
    const float* __restrict__ e,
    float* __restrict__ out,
    int n, int jchunks, int itiles)
{
    __shared__ float2 te[JCH];
    __shared__ float  red[BLOCK];
    __shared__ int    flag;

    const int jc  = blockIdx.x;
    const int it  = blockIdx.y;
    const int tid = threadIdx.x;

    // ---- stage j-chunk: (t_j, exp(theta_j)) as float2 -> 1 LDS.64 broadcast
    const int j0 = jc * JCH;
    if (tid < JCH)
        te[tid] = make_float2(t[j0 + tid], expf(risk[j0 + tid]));
    __syncthreads();

    // ---- pair phase: 2048 i's per block, 4 per thread
    const int ibase = it * (BLOCK * IPT);
    const int i0    = ibase + tid;

    float ti[IPT];
    float s[IPT];
#pragma unroll
    for (int k = 0; k < IPT; k++) {
        ti[k] = t[i0 + k * BLOCK];            // coalesced
        s[k]  = 0.0f;
    }

#pragma unroll 4
    for (int j = 0; j < JCH; j++) {
        const float2 p = te[j];               // broadcast
#pragma unroll
        for (int k = 0; k < IPT; k++) {
            float m;                          // mask as DATA: FSET, lat 4
            asm("set.ge.f32.f32 %0, %1, %2;" : "=f"(m) : "f"(p.x), "f"(ti[k]));
            s[k] = fmaf(m, p.y, s[k]);        // FFMA, lat 4
        }
    }

#pragma unroll
    for (int k = 0; k < IPT; k++)
        g_part[jc * n + i0 + k * BLOCK] = s[k];

    // ---- make partials visible, elect last block of this i-tile
    __threadfence();
    __syncthreads();
    if (tid == 0) {
        int v = atomicAdd(&g_done_it[it], 1);
        flag = (v == jchunks - 1);
    }
    __syncthreads();
    if (!flag) return;

    // ---- finalize this i-tile (only last-arriving (jc, it) block)
    __threadfence();   // acquire: all jc partials for this tile visible

    float S[IPT];
#pragma unroll
    for (int k = 0; k < IPT; k++) S[k] = 0.0f;

#pragma unroll 4
    for (int c = 0; c < jchunks; c++) {       // c outer, k inner -> MLP >= 16
        const float* base = &g_part[c * n + i0];
#pragma unroll
        for (int k = 0; k < IPT; k++)
            S[k] += __ldcg(&base[k * BLOCK]); // fixed order per i
    }

    float acc = 0.0f;
#pragma unroll
    for (int k = 0; k < IPT; k++) {
        const int i = i0 + k * BLOCK;
        acc += (risk[i] - logf(S[k] + EPS_F)) * e[i];
    }

    // fixed-order block reduction of 512 values
    red[tid] = acc;
    __syncthreads();
#pragma unroll
    for (int off = BLOCK / 2; off >= 64; off >>= 1) {
        if (tid < off) red[tid] += red[tid + off];
        __syncthreads();
    }
    if (tid < 32) {
        float v = red[tid] + red[tid + 32];
#pragma unroll
        for (int off = 16; off > 0; off >>= 1)
            v += __shfl_down_sync(0xffffffffu, v, off);

        if (tid == 0) {
            g_tsum[it] = v;
            __threadfence();
            if (atomicAdd(&g_done_final, 1) == itiles - 1) {
                // very last finalizer: fixed-order final sum + reset
                __threadfence();
                float total = 0.0f;
                for (int k = 0; k < itiles; k++)
                    total += __ldcg(&g_tsum[k]);
                out[0] = -total / (float)n;

                g_done_final = 0;
                for (int k = 0; k < itiles; k++) g_done_it[k] = 0;
                __threadfence();
            }
        }
    }
}

// ---------------------------------------------------------------- launch
extern "C" void kernel_launch(void* const* d_in, const int* in_sizes, int n_in,
                              void* d_out, int out_size) {
    const float* risk = (const float*)d_in[0];
    const float* t    = (const float*)d_in[1];
    const float* e    = (const float*)d_in[2];
    float* out = (float*)d_out;

    const int n = in_sizes[0];                 // 8192
    const int jchunks = n / JCH;               // 32
    const int itiles  = n / (BLOCK * IPT);     // 4

    cox_fused_kernel<<<dim3(jchunks, itiles), BLOCK>>>(
        risk, t, e, out, n, jchunks, itiles);
}